// round 14
// baseline (speedup 1.0000x reference)
#include <cuda_runtime.h>
#include <cstdint>

#define T_STEPS 200
#define BATCH   256
#define IN_F    512
#define H1      1024
#define H2      1024
#define H3      512
#define NCTA    128
#define SW2     33      // phase-2/3 weight row stride (floats)
#define IDXCAP  544     // per-(t,row) index list capacity (16B-aligned rows)

// ---------------- persistent device state ------------------------------------
__device__ float g_m3sum[BATCH * H3];
__device__ int   g_cnt[3];
__device__ unsigned g_xbits[T_STEPS * BATCH * 16];        // [t][row][16 words]
__device__ unsigned short g_xidx[T_STEPS][BATCH][IDXCAP]; // compacted k lists
__device__ int g_xcnt[T_STEPS][BATCH];                    // padded counts (mult of 8)
__device__ unsigned g_b1[T_STEPS][BATCH][32];             // spk1 history
__device__ unsigned g_b2[T_STEPS][BATCH][32];             // spk2 history
__device__ volatile int g_arrive[NCTA];
__device__ volatile int g_release;

// ---------------- prep ---------------------------------------------------------
__global__ void init_kernel() {
    int i = blockIdx.x * blockDim.x + threadIdx.x;
    if (i < 3) g_cnt[i] = 0;
    if (i < NCTA) g_arrive[i] = 0;
    if (i == 0) g_release = 0;
}

__global__ void build_xbits(const float* __restrict__ s) {
    int j = blockIdx.x * blockDim.x + threadIdx.x;
    if (j < T_STEPS * BATCH * 16) {
        const float4* p = (const float4*)(s + (size_t)j * 32);
        unsigned b = 0;
#pragma unroll
        for (int q = 0; q < 8; q++) {
            float4 v = p[q];
            b |= (v.x > 0.5f ? 1u : 0u) << (4 * q + 0);
            b |= (v.y > 0.5f ? 1u : 0u) << (4 * q + 1);
            b |= (v.z > 0.5f ? 1u : 0u) << (4 * q + 2);
            b |= (v.w > 0.5f ? 1u : 0u) << (4 * q + 3);
        }
        g_xbits[j] = b;
    }
}

// one thread per (t,row): compact active k's (ascending), pad to multiple of 8
__global__ void build_xidx() {
    int id = blockIdx.x * blockDim.x + threadIdx.x;
    if (id >= T_STEPS * BATCH) return;
    int t = id / BATCH, r = id % BATCH;
    const unsigned* wp = &g_xbits[(size_t)id * 16];
    unsigned short* dst = g_xidx[t][r];
    int n = 0;
#pragma unroll
    for (int w = 0; w < 16; w++) {
        unsigned bits = wp[w];
        while (bits) {
            int b = __ffs(bits) - 1;
            bits &= bits - 1;
            dst[n++] = (unsigned short)(w * 32 + b);
        }
    }
    int np = (n + 7) & ~7;
    while (n < np) dst[n++] = (unsigned short)IN_F;   // dummy -> zero weight row
    g_xcnt[t][r] = np;
}

// ---------------- global barrier ----------------------------------------------
__device__ __forceinline__ void gbar(int gen, int cta, int tid) {
    __syncthreads();
    if (tid == 0) { __threadfence(); g_arrive[cta] = gen; }
    if (cta == 0 && tid < 32) {
        for (;;) {
            int v0 = g_arrive[tid];
            int v1 = g_arrive[tid + 32];
            int v2 = g_arrive[tid + 64];
            int v3 = g_arrive[tid + 96];
            if (__all_sync(0xFFFFFFFFu,
                           v0 >= gen && v1 >= gen && v2 >= gen && v3 >= gen))
                break;
        }
        if (tid == 0) { __threadfence(); g_release = gen; }
    }
    if (tid == 0) {
        while (g_release < gen) { }
        __threadfence();
    }
    __syncthreads();
}

// ---------------- LIF scalar step ----------------------------------------------
__device__ __forceinline__ unsigned lif1(float& m, float a, float beta) {
    float reset = (m > 1.0f) ? 1.0f : 0.0f;    // spike(m_prev - 1)
    m = beta * m + a - reset;                  // subtract-reset
    return (m > 1.0f) ? 1u : 0u;               // spike(m_new - 1)
}

// ---------------- THE persistent kernel ----------------------------------------
__global__ void __launch_bounds__(512, 1)
snn_phased(const float* __restrict__ W1, const float* __restrict__ b1,
           const float* __restrict__ W2, const float* __restrict__ b2,
           const float* __restrict__ W3, const float* __restrict__ b3)
{
    extern __shared__ float Wsm[];   // phase1: u32 bf16x2 [513][32]; p2/3: [1024][33]
    __shared__ int sr_[3][16];

    const int tid  = threadIdx.x;
    const int cta  = blockIdx.x;
    const int wid  = tid >> 5;
    const int lane = tid & 31;

    const float BETA1 = 0.81873075307798182f;  // exp(-1/5)
    const float BETA2 = 0.90483741803595957f;  // exp(-1/10)
    const float BETA3 = 0.95122942450071402f;  // exp(-1/20)

    int c1 = 0, c2 = 0, c3 = 0;

    // ================= phase 1: layer 1 (64 cols x 32 rows per CTA) ==========
    {
        unsigned* Wb = (unsigned*)Wsm;  // Wb[k*32+l] = bf16x2(W[c0+l][k], W[c0+32+l][k])
        const int cb = cta & 15;        // 16 col-blocks of 64
        const int rg = cta >> 4;        // 8 row-groups of 32
        // stage: thread handles l = tid&31, k strided — conflict-free STS
        for (int idx = tid; idx < 32 * IN_F; idx += 512) {
            int l = idx & 31, k = idx >> 5;
            float v0 = W1[(size_t)(cb * 64 + l) * IN_F + k];
            float v1 = W1[(size_t)(cb * 64 + 32 + l) * IN_F + k];
            // round-to-nearest bf16 for both halves
            unsigned u0 = __float_as_uint(v0);
            u0 = (u0 + 0x7FFFu + ((u0 >> 16) & 1u)) >> 16;
            unsigned u1 = __float_as_uint(v1);
            u1 = ((u1 + 0x7FFFu + ((u1 >> 16) & 1u)) >> 16) << 16;
            Wb[k * 32 + l] = (u0 & 0xFFFFu) | u1;
        }
        if (tid < 32) Wb[IN_F * 32 + tid] = 0u;    // dummy row k = IN_F

        const int r0 = rg * 32 + wid * 2;          // warp owns rows r0, r0+1
        const float bs0 = b1[cb * 64 + lane];
        const float bs1 = b1[cb * 64 + 32 + lane];
        float m[2][2] = {{0.f, 0.f}, {0.f, 0.f}};
        __syncthreads();

        // prefetch t=0 counts + first idx groups (same-address LDG, all lanes)
        int pn[2]; uint4 pg[2];
#pragma unroll
        for (int i = 0; i < 2; i++) {
            pn[i] = __ldcg(&g_xcnt[0][r0 + i]);
            pg[i] = __ldcg((const uint4*)g_xidx[0][r0 + i]);
        }

        for (int t = 0; t < T_STEPS; t++) {
            int  nn[2] = {pn[0], pn[1]};
            uint4 g0[2] = {pg[0], pg[1]};
            if (t + 1 < T_STEPS) {
#pragma unroll
                for (int i = 0; i < 2; i++) {
                    pn[i] = __ldcg(&g_xcnt[t + 1][r0 + i]);
                    pg[i] = __ldcg((const uint4*)g_xidx[t + 1][r0 + i]);
                }
            }
#pragma unroll
            for (int i = 0; i < 2; i++) {
                // 4 independent chains: (even bits, odd bits) x (col set 0, 1)
                float a0e = bs0, a1e = bs1, a0o = 0.f, a1o = 0.f;
                const uint4* lp = (const uint4*)g_xidx[t][r0 + i];  // 8 idx/uint4
                const int ng = nn[i] >> 3;
                uint4 g = g0[i];
                for (int j = 0; j < ng; j++) {
                    uint4 gn = g;
                    if (j + 1 < ng) gn = __ldcg(lp + j + 1);
                    unsigned k, wv;
#define GATHER(word, sh, A0, A1) \
                    k = ((word) >> (sh)) & 0xFFFFu; \
                    wv = Wb[k * 32 + lane]; \
                    A0 += __uint_as_float(wv << 16); \
                    A1 += __uint_as_float(wv & 0xFFFF0000u);
                    GATHER(g.x, 0,  a0e, a1e)  GATHER(g.x, 16, a0o, a1o)
                    GATHER(g.y, 0,  a0e, a1e)  GATHER(g.y, 16, a0o, a1o)
                    GATHER(g.z, 0,  a0e, a1e)  GATHER(g.z, 16, a0o, a1o)
                    GATHER(g.w, 0,  a0e, a1e)  GATHER(g.w, 16, a0o, a1o)
#undef GATHER
                    g = gn;
                }
                float a0 = a0e + a0o;
                float a1 = a1e + a1o;
                unsigned s0 = lif1(m[i][0], a0, BETA1);
                unsigned s1 = lif1(m[i][1], a1, BETA1);
                unsigned w0 = __ballot_sync(0xFFFFFFFFu, s0);
                unsigned w1 = __ballot_sync(0xFFFFFFFFu, s1);
                if (lane == 0) {
                    c1 += __popc(w0) + __popc(w1);
                    *(unsigned long long*)&g_b1[t][r0 + i][cb * 2] =
                        ((unsigned long long)w1 << 32) | w0;
                }
            }
        }
    }
    gbar(1, cta, tid);

    // ================= phase 2: layer 2 (32 cols x 64 rows per CTA) ==========
    {
        const int cb = cta & 31;        // 32 col-blocks of 32
        const int rg = cta >> 5;        // 4 row-groups of 64
        for (int idx = tid; idx < 32 * H1; idx += 512) {
            int n = idx >> 10, k = idx & (H1 - 1);
            Wsm[k * SW2 + n] = W2[(size_t)(cb * 32 + n) * H1 + k];
        }
        const int r0 = rg * 64 + wid * 4;          // warp owns rows r0..r0+3
        const float bsv = b2[cb * 32 + lane];
        float m[4] = {0.f, 0.f, 0.f, 0.f};
        __syncthreads();

        unsigned cur[4];
#pragma unroll
        for (int c = 0; c < 4; c++) cur[c] = __ldcg(&g_b1[0][r0 + c][lane]);
        for (int t = 0; t < T_STEPS; t++) {
            unsigned nxt[4] = {0, 0, 0, 0};
            if (t + 1 < T_STEPS) {
#pragma unroll
                for (int c = 0; c < 4; c++)
                    nxt[c] = __ldcg(&g_b1[t + 1][r0 + c][lane]);
            }
#pragma unroll
            for (int i = 0; i < 4; i++) {
                float a = bsv;
                unsigned nz = __ballot_sync(0xFFFFFFFFu, cur[i] != 0u);
                while (nz) {
                    int w = __ffs(nz) - 1;
                    nz &= nz - 1;
                    unsigned bits = __shfl_sync(0xFFFFFFFFu, cur[i], w);
                    while (bits) {
                        int b = __ffs(bits) - 1;
                        bits &= bits - 1;
                        a += Wsm[(w * 32 + b) * SW2 + lane];
                    }
                }
                unsigned s = lif1(m[i], a, BETA2);
                unsigned w0 = __ballot_sync(0xFFFFFFFFu, s);
                if (lane == 0) {
                    c2 += __popc(w0);
                    g_b2[t][r0 + i][cb] = w0;
                }
            }
#pragma unroll
            for (int c = 0; c < 4; c++) cur[c] = nxt[c];
        }
    }
    gbar(2, cta, tid);

    // ================= phase 3: layer 3 (32 cols x 32 rows per CTA) ==========
    {
        const int cb = cta & 15;        // 16 col-blocks of 32
        const int rg = cta >> 4;        // 8 row-groups of 32
        for (int idx = tid; idx < 32 * H2; idx += 512) {
            int n = idx >> 10, k = idx & (H2 - 1);
            Wsm[k * SW2 + n] = W3[(size_t)(cb * 32 + n) * H2 + k];
        }
        const int r0 = rg * 32 + wid * 2;          // warp owns rows r0, r0+1
        const float bsv = b3[cb * 32 + lane];
        float m[2] = {0.f, 0.f}, ms[2] = {0.f, 0.f};
        __syncthreads();

        unsigned cur[2];
#pragma unroll
        for (int c = 0; c < 2; c++) cur[c] = __ldcg(&g_b2[0][r0 + c][lane]);
        for (int t = 0; t < T_STEPS; t++) {
            unsigned nxt[2] = {0, 0};
            if (t + 1 < T_STEPS) {
#pragma unroll
                for (int c = 0; c < 2; c++)
                    nxt[c] = __ldcg(&g_b2[t + 1][r0 + c][lane]);
            }
#pragma unroll
            for (int i = 0; i < 2; i++) {
                float a = bsv;
                unsigned nz = __ballot_sync(0xFFFFFFFFu, cur[i] != 0u);
                while (nz) {
                    int w = __ffs(nz) - 1;
                    nz &= nz - 1;
                    unsigned bits = __shfl_sync(0xFFFFFFFFu, cur[i], w);
                    while (bits) {
                        int b = __ffs(bits) - 1;
                        bits &= bits - 1;
                        a += Wsm[(w * 32 + b) * SW2 + lane];
                    }
                }
                unsigned s = lif1(m[i], a, BETA3);
                ms[i] += m[i];
                unsigned w0 = __ballot_sync(0xFFFFFFFFu, s);
                if (lane == 0) c3 += __popc(w0);
            }
#pragma unroll
            for (int c = 0; c < 2; c++) cur[c] = nxt[c];
        }
#pragma unroll
        for (int i = 0; i < 2; i++)
            g_m3sum[(size_t)(r0 + i) * H3 + cb * 32 + lane] = ms[i];
    }

    // ---- exact spike counts ----
    if (lane == 0) { sr_[0][wid] = c1; sr_[1][wid] = c2; sr_[2][wid] = c3; }
    __syncthreads();
    if (tid < 3) {
        int s = 0;
#pragma unroll
        for (int w = 0; w < 16; w++) s += sr_[tid][w];
        atomicAdd(&g_cnt[tid], s);
    }
}

// ---------------- readout -------------------------------------------------------
__global__ void final_kernel(const float* __restrict__ Wr,
                             const float* __restrict__ br,
                             float* __restrict__ out)
{
    const int b = blockIdx.x;
    const int t = threadIdx.x;
    float a0 = 0.f, a1 = 0.f;
    for (int j = t; j < H3; j += 128) {
        float v = g_m3sum[(size_t)b * H3 + j] / (float)T_STEPS;
        a0 = fmaf(v, Wr[j],      a0);
        a1 = fmaf(v, Wr[H3 + j], a1);
    }
    __shared__ float s0[128], s1[128];
    s0[t] = a0; s1[t] = a1;
    __syncthreads();
    for (int o = 64; o > 0; o >>= 1) {
        if (t < o) { s0[t] += s0[t + o]; s1[t] += s1[t + o]; }
        __syncthreads();
    }
    if (t == 0) {
        out[b * 2 + 0] = s0[0] + br[0];
        out[b * 2 + 1] = s1[0] + br[1];
    }
    if (b == 0 && t < 3) {
        float denom = (t == 0) ? (float)((double)T_STEPS * BATCH * H1)
                    : (t == 1) ? (float)((double)T_STEPS * BATCH * H2)
                               : (float)((double)T_STEPS * BATCH * H3);
        out[BATCH * 2 + t] = (float)g_cnt[t] / denom;
    }
}

// ---------------- launch --------------------------------------------------------
extern "C" void kernel_launch(void* const* d_in, const int* in_sizes, int n_in,
                              void* d_out, int out_size)
{
    const float* spikes = (const float*)d_in[0];
    const float* W1 = (const float*)d_in[1];
    const float* b1 = (const float*)d_in[2];
    const float* W2 = (const float*)d_in[3];
    const float* b2 = (const float*)d_in[4];
    const float* W3 = (const float*)d_in[5];
    const float* b3 = (const float*)d_in[6];
    const float* Wr = (const float*)d_in[7];
    const float* br = (const float*)d_in[8];
    float* out = (float*)d_out;

    // phase1 needs (512+1)*32*4 = 65,664 B; phase2/3 need 1024*33*4 = 135,168 B
    const int DSMEM = 1024 * SW2 * 4;
    cudaFuncSetAttribute(snn_phased,
                         cudaFuncAttributeMaxDynamicSharedMemorySize, DSMEM);

    init_kernel<<<1, 256>>>();
    {
        int n = T_STEPS * BATCH * 16;
        build_xbits<<<(n + 255) / 256, 256>>>(spikes);
        build_xidx<<<(T_STEPS * BATCH + 255) / 256, 256>>>();
    }
    snn_phased<<<NCTA, 512, DSMEM>>>(W1, b1, W2, b2, W3, b3);
    final_kernel<<<BATCH, 128>>>(Wr, br, out);
}

// round 15
// speedup vs baseline: 1.2667x; 1.2667x over previous
#include <cuda_runtime.h>
#include <cstdint>

#define T_STEPS 200
#define BATCH   256
#define IN_F    512
#define H1      1024
#define H2      1024
#define H3      512
#define NCTA    128
#define SW2     33      // phase-2/3 weight row stride (floats)
#define IDXCAP  544     // per-(t,row) index list capacity (16B-aligned rows)

// ---------------- persistent device state ------------------------------------
__device__ float g_m3sum[BATCH * H3];
__device__ int   g_cnt[3];
__device__ unsigned g_xbits[T_STEPS * BATCH * 16];        // [t][row][16 words]
__device__ unsigned short g_xidx[T_STEPS][BATCH][IDXCAP]; // compacted k lists
__device__ int g_xcnt[T_STEPS][BATCH];                    // padded counts (mult of 8)
__device__ unsigned g_b1[T_STEPS][BATCH][32];             // spk1 history
__device__ unsigned g_b2[T_STEPS][BATCH][32];             // spk2 history
__device__ volatile int g_arrive[NCTA];
__device__ volatile int g_release;

// ---------------- prep ---------------------------------------------------------
__global__ void init_kernel() {
    int i = blockIdx.x * blockDim.x + threadIdx.x;
    if (i < 3) g_cnt[i] = 0;
    if (i < NCTA) g_arrive[i] = 0;
    if (i == 0) g_release = 0;
}

__global__ void build_xbits(const float* __restrict__ s) {
    int j = blockIdx.x * blockDim.x + threadIdx.x;
    if (j < T_STEPS * BATCH * 16) {
        const float4* p = (const float4*)(s + (size_t)j * 32);
        unsigned b = 0;
#pragma unroll
        for (int q = 0; q < 8; q++) {
            float4 v = p[q];
            b |= (v.x > 0.5f ? 1u : 0u) << (4 * q + 0);
            b |= (v.y > 0.5f ? 1u : 0u) << (4 * q + 1);
            b |= (v.z > 0.5f ? 1u : 0u) << (4 * q + 2);
            b |= (v.w > 0.5f ? 1u : 0u) << (4 * q + 3);
        }
        g_xbits[j] = b;
    }
}

// one thread per (t,row): compact active k's (ascending), pad to multiple of 8
__global__ void build_xidx() {
    int id = blockIdx.x * blockDim.x + threadIdx.x;
    if (id >= T_STEPS * BATCH) return;
    int t = id / BATCH, r = id % BATCH;
    const unsigned* wp = &g_xbits[(size_t)id * 16];
    unsigned short* dst = g_xidx[t][r];
    int n = 0;
#pragma unroll
    for (int w = 0; w < 16; w++) {
        unsigned bits = wp[w];
        while (bits) {
            int b = __ffs(bits) - 1;
            bits &= bits - 1;
            dst[n++] = (unsigned short)(w * 32 + b);
        }
    }
    int np = (n + 7) & ~7;
    while (n < np) dst[n++] = (unsigned short)IN_F;   // dummy -> zero weight row
    g_xcnt[t][r] = np;
}

// ---------------- global barrier ----------------------------------------------
__device__ __forceinline__ void gbar(int gen, int cta, int tid) {
    __syncthreads();
    if (tid == 0) { __threadfence(); g_arrive[cta] = gen; }
    if (cta == 0 && tid < 32) {
        for (;;) {
            int v0 = g_arrive[tid];
            int v1 = g_arrive[tid + 32];
            int v2 = g_arrive[tid + 64];
            int v3 = g_arrive[tid + 96];
            if (__all_sync(0xFFFFFFFFu,
                           v0 >= gen && v1 >= gen && v2 >= gen && v3 >= gen))
                break;
        }
        if (tid == 0) { __threadfence(); g_release = gen; }
    }
    if (tid == 0) {
        while (g_release < gen) { }
        __threadfence();
    }
    __syncthreads();
}

// ---------------- LIF scalar step ----------------------------------------------
__device__ __forceinline__ unsigned lif1(float& m, float a, float beta) {
    float reset = (m > 1.0f) ? 1.0f : 0.0f;    // spike(m_prev - 1)
    m = beta * m + a - reset;                  // subtract-reset
    return (m > 1.0f) ? 1u : 0u;               // spike(m_new - 1)
}

// ---------------- THE persistent kernel (1024 threads = 32 warps) --------------
__global__ void __launch_bounds__(1024, 1)
snn_phased(const float* __restrict__ W1, const float* __restrict__ b1,
           const float* __restrict__ W2, const float* __restrict__ b2,
           const float* __restrict__ W3, const float* __restrict__ b3)
{
    extern __shared__ float Wsm[];   // phase1: u32 bf16x2 [513][32]; p2/3: [1024][33]
    __shared__ int sr_[3][32];

    const int tid  = threadIdx.x;
    const int cta  = blockIdx.x;
    const int wid  = tid >> 5;
    const int lane = tid & 31;

    const float BETA1 = 0.81873075307798182f;  // exp(-1/5)
    const float BETA2 = 0.90483741803595957f;  // exp(-1/10)
    const float BETA3 = 0.95122942450071402f;  // exp(-1/20)

    int c1 = 0, c2 = 0, c3 = 0;

    // ================= phase 1: layer 1 (64 cols x 32 rows per CTA) ==========
    {
        unsigned* Wb = (unsigned*)Wsm;  // Wb[k*32+l] = bf16x2(W[c0+l][k], W[c0+32+l][k])
        const int cb = cta & 15;        // 16 col-blocks of 64
        const int rg = cta >> 4;        // 8 row-groups of 32
        // stage: thread handles l = idx&31, k = idx>>5 — conflict-free STS
        for (int idx = tid; idx < 32 * IN_F; idx += 1024) {
            int l = idx & 31, k = idx >> 5;
            float v0 = W1[(size_t)(cb * 64 + l) * IN_F + k];
            float v1 = W1[(size_t)(cb * 64 + 32 + l) * IN_F + k];
            // round-to-nearest bf16 for both halves
            unsigned u0 = __float_as_uint(v0);
            u0 = (u0 + 0x7FFFu + ((u0 >> 16) & 1u)) >> 16;
            unsigned u1 = __float_as_uint(v1);
            u1 = ((u1 + 0x7FFFu + ((u1 >> 16) & 1u)) >> 16) << 16;
            Wb[k * 32 + l] = (u0 & 0xFFFFu) | u1;
        }
        if (tid < 32) Wb[IN_F * 32 + tid] = 0u;    // dummy row k = IN_F

        const int r0 = rg * 32 + wid;              // warp owns ONE row
        const float bs0 = b1[cb * 64 + lane];
        const float bs1 = b1[cb * 64 + 32 + lane];
        float m0 = 0.f, m1 = 0.f;
        __syncthreads();

        // prefetch t=0 count + first idx group (same-address LDG, all lanes)
        int pn = __ldcg(&g_xcnt[0][r0]);
        uint4 pg = __ldcg((const uint4*)g_xidx[0][r0]);

        for (int t = 0; t < T_STEPS; t++) {
            const int  nn = pn;
            uint4 g = pg;
            if (t + 1 < T_STEPS) {
                pn = __ldcg(&g_xcnt[t + 1][r0]);
                pg = __ldcg((const uint4*)g_xidx[t + 1][r0]);
            }
            // 4 independent chains: (even bits, odd bits) x (col set 0, 1)
            float a0e = bs0, a1e = bs1, a0o = 0.f, a1o = 0.f;
            const uint4* lp = (const uint4*)g_xidx[t][r0];   // 8 idx/uint4
            const int ng = nn >> 3;
            for (int j = 0; j < ng; j++) {
                uint4 gn = g;
                if (j + 1 < ng) gn = __ldcg(lp + j + 1);
                unsigned k, wv;
#define GATHER(word, sh, A0, A1) \
                k = ((word) >> (sh)) & 0xFFFFu; \
                wv = Wb[k * 32 + lane]; \
                A0 += __uint_as_float(wv << 16); \
                A1 += __uint_as_float(wv & 0xFFFF0000u);
                GATHER(g.x, 0,  a0e, a1e)  GATHER(g.x, 16, a0o, a1o)
                GATHER(g.y, 0,  a0e, a1e)  GATHER(g.y, 16, a0o, a1o)
                GATHER(g.z, 0,  a0e, a1e)  GATHER(g.z, 16, a0o, a1o)
                GATHER(g.w, 0,  a0e, a1e)  GATHER(g.w, 16, a0o, a1o)
#undef GATHER
                g = gn;
            }
            float a0 = a0e + a0o;
            float a1 = a1e + a1o;
            unsigned s0 = lif1(m0, a0, BETA1);
            unsigned s1 = lif1(m1, a1, BETA1);
            unsigned w0 = __ballot_sync(0xFFFFFFFFu, s0);
            unsigned w1 = __ballot_sync(0xFFFFFFFFu, s1);
            if (lane == 0) {
                c1 += __popc(w0) + __popc(w1);
                *(unsigned long long*)&g_b1[t][r0][cb * 2] =
                    ((unsigned long long)w1 << 32) | w0;
            }
        }
    }
    gbar(1, cta, tid);

    // ================= phase 2: layer 2 (32 cols x 64 rows per CTA) ==========
    {
        const int cb = cta & 31;        // 32 col-blocks of 32
        const int rg = cta >> 5;        // 4 row-groups of 64
        for (int idx = tid; idx < 32 * H1; idx += 1024) {
            int n = idx >> 10, k = idx & (H1 - 1);
            Wsm[k * SW2 + n] = W2[(size_t)(cb * 32 + n) * H1 + k];
        }
        const int r0 = rg * 64 + wid * 2;          // warp owns rows r0, r0+1
        const float bsv = b2[cb * 32 + lane];
        float m[2] = {0.f, 0.f};
        __syncthreads();

        unsigned cur[2];
#pragma unroll
        for (int c = 0; c < 2; c++) cur[c] = __ldcg(&g_b1[0][r0 + c][lane]);
        for (int t = 0; t < T_STEPS; t++) {
            unsigned nxt[2] = {0, 0};
            if (t + 1 < T_STEPS) {
#pragma unroll
                for (int c = 0; c < 2; c++)
                    nxt[c] = __ldcg(&g_b1[t + 1][r0 + c][lane]);
            }
#pragma unroll
            for (int i = 0; i < 2; i++) {
                float a = bsv;
                unsigned nz = __ballot_sync(0xFFFFFFFFu, cur[i] != 0u);
                while (nz) {
                    int w = __ffs(nz) - 1;
                    nz &= nz - 1;
                    unsigned bits = __shfl_sync(0xFFFFFFFFu, cur[i], w);
                    while (bits) {
                        int b = __ffs(bits) - 1;
                        bits &= bits - 1;
                        a += Wsm[(w * 32 + b) * SW2 + lane];
                    }
                }
                unsigned s = lif1(m[i], a, BETA2);
                unsigned w0 = __ballot_sync(0xFFFFFFFFu, s);
                if (lane == 0) {
                    c2 += __popc(w0);
                    g_b2[t][r0 + i][cb] = w0;
                }
            }
#pragma unroll
            for (int c = 0; c < 2; c++) cur[c] = nxt[c];
        }
    }
    gbar(2, cta, tid);

    // ================= phase 3: layer 3 (32 cols x 32 rows per CTA) ==========
    {
        const int cb = cta & 15;        // 16 col-blocks of 32
        const int rg = cta >> 4;        // 8 row-groups of 32
        for (int idx = tid; idx < 32 * H2; idx += 1024) {
            int n = idx >> 10, k = idx & (H2 - 1);
            Wsm[k * SW2 + n] = W3[(size_t)(cb * 32 + n) * H2 + k];
        }
        const int r0 = rg * 32 + wid;              // warp owns ONE row
        const float bsv = b3[cb * 32 + lane];
        float m3v = 0.f, msv = 0.f;
        __syncthreads();

        unsigned cur = __ldcg(&g_b2[0][r0][lane]);
        for (int t = 0; t < T_STEPS; t++) {
            unsigned nxt = 0;
            if (t + 1 < T_STEPS) nxt = __ldcg(&g_b2[t + 1][r0][lane]);
            float a = bsv;
            unsigned nz = __ballot_sync(0xFFFFFFFFu, cur != 0u);
            while (nz) {
                int w = __ffs(nz) - 1;
                nz &= nz - 1;
                unsigned bits = __shfl_sync(0xFFFFFFFFu, cur, w);
                while (bits) {
                    int b = __ffs(bits) - 1;
                    bits &= bits - 1;
                    a += Wsm[(w * 32 + b) * SW2 + lane];
                }
            }
            unsigned s = lif1(m3v, a, BETA3);
            msv += m3v;
            unsigned w0 = __ballot_sync(0xFFFFFFFFu, s);
            if (lane == 0) c3 += __popc(w0);
            cur = nxt;
        }
        g_m3sum[(size_t)r0 * H3 + cb * 32 + lane] = msv;
    }

    // ---- exact spike counts ----
    if (lane == 0) { sr_[0][wid] = c1; sr_[1][wid] = c2; sr_[2][wid] = c3; }
    __syncthreads();
    if (tid < 3) {
        int s = 0;
#pragma unroll
        for (int w = 0; w < 32; w++) s += sr_[tid][w];
        atomicAdd(&g_cnt[tid], s);
    }
}

// ---------------- readout -------------------------------------------------------
__global__ void final_kernel(const float* __restrict__ Wr,
                             const float* __restrict__ br,
                             float* __restrict__ out)
{
    const int b = blockIdx.x;
    const int t = threadIdx.x;
    float a0 = 0.f, a1 = 0.f;
    for (int j = t; j < H3; j += 128) {
        float v = g_m3sum[(size_t)b * H3 + j] / (float)T_STEPS;
        a0 = fmaf(v, Wr[j],      a0);
        a1 = fmaf(v, Wr[H3 + j], a1);
    }
    __shared__ float s0[128], s1[128];
    s0[t] = a0; s1[t] = a1;
    __syncthreads();
    for (int o = 64; o > 0; o >>= 1) {
        if (t < o) { s0[t] += s0[t + o]; s1[t] += s1[t + o]; }
        __syncthreads();
    }
    if (t == 0) {
        out[b * 2 + 0] = s0[0] + br[0];
        out[b * 2 + 1] = s1[0] + br[1];
    }
    if (b == 0 && t < 3) {
        float denom = (t == 0) ? (float)((double)T_STEPS * BATCH * H1)
                    : (t == 1) ? (float)((double)T_STEPS * BATCH * H2)
                               : (float)((double)T_STEPS * BATCH * H3);
        out[BATCH * 2 + t] = (float)g_cnt[t] / denom;
    }
}

// ---------------- launch --------------------------------------------------------
extern "C" void kernel_launch(void* const* d_in, const int* in_sizes, int n_in,
                              void* d_out, int out_size)
{
    const float* spikes = (const float*)d_in[0];
    const float* W1 = (const float*)d_in[1];
    const float* b1 = (const float*)d_in[2];
    const float* W2 = (const float*)d_in[3];
    const float* b2 = (const float*)d_in[4];
    const float* W3 = (const float*)d_in[5];
    const float* b3 = (const float*)d_in[6];
    const float* Wr = (const float*)d_in[7];
    const float* br = (const float*)d_in[8];
    float* out = (float*)d_out;

    // phase1 needs (512+1)*32*4 = 65,664 B; phase2/3 need 1024*33*4 = 135,168 B
    const int DSMEM = 1024 * SW2 * 4;
    cudaFuncSetAttribute(snn_phased,
                         cudaFuncAttributeMaxDynamicSharedMemorySize, DSMEM);

    init_kernel<<<1, 256>>>();
    {
        int n = T_STEPS * BATCH * 16;
        build_xbits<<<(n + 255) / 256, 256>>>(spikes);
        build_xidx<<<(T_STEPS * BATCH + 255) / 256, 256>>>();
    }
    snn_phased<<<NCTA, 1024, DSMEM>>>(W1, b1, W2, b2, W3, b3);
    final_kernel<<<BATCH, 128>>>(Wr, br, out);
}

// round 16
// speedup vs baseline: 1.4491x; 1.1440x over previous
#include <cuda_runtime.h>
#include <cstdint>

#define T_STEPS 200
#define BATCH   256
#define IN_F    512
#define H1      1024
#define H2      1024
#define H3      512
#define NCTA    128
#define SW2     33      // phase-2/3 weight row stride (floats)
#define IDXCAP  544     // per-(t,row) offset list capacity (16B-aligned rows)

// ---------------- persistent device state ------------------------------------
__device__ float g_m3sum[BATCH * H3];
__device__ int   g_cnt[3];
__device__ unsigned g_xbits[T_STEPS * BATCH * 16];        // [t][row][16 words]
__device__ unsigned g_xofs[T_STEPS][BATCH][IDXCAP];       // byte offsets k*128
__device__ int g_xcnt[T_STEPS][BATCH];                    // counts (mult of 8)
__device__ unsigned g_b1[T_STEPS][BATCH][32];             // spk1 history
__device__ unsigned g_b2[T_STEPS][BATCH][32];             // spk2 history
__device__ volatile int g_arrive[NCTA];
__device__ volatile int g_release;

// ---------------- prep ---------------------------------------------------------
__global__ void init_kernel() {
    int i = blockIdx.x * blockDim.x + threadIdx.x;
    if (i < 3) g_cnt[i] = 0;
    if (i < NCTA) g_arrive[i] = 0;
    if (i == 0) g_release = 0;
}

__global__ void build_xbits(const float* __restrict__ s) {
    int j = blockIdx.x * blockDim.x + threadIdx.x;
    if (j < T_STEPS * BATCH * 16) {
        const float4* p = (const float4*)(s + (size_t)j * 32);
        unsigned b = 0;
#pragma unroll
        for (int q = 0; q < 8; q++) {
            float4 v = p[q];
            b |= (v.x > 0.5f ? 1u : 0u) << (4 * q + 0);
            b |= (v.y > 0.5f ? 1u : 0u) << (4 * q + 1);
            b |= (v.z > 0.5f ? 1u : 0u) << (4 * q + 2);
            b |= (v.w > 0.5f ? 1u : 0u) << (4 * q + 3);
        }
        g_xbits[j] = b;
    }
}

// one thread per (t,row): compact active k's as BYTE OFFSETS (k*128), ascending,
// padded to a multiple of 8 with dummy offsets pointing at the zeroed row.
__global__ void build_xidx() {
    int id = blockIdx.x * blockDim.x + threadIdx.x;
    if (id >= T_STEPS * BATCH) return;
    int t = id / BATCH, r = id % BATCH;
    const unsigned* wp = &g_xbits[(size_t)id * 16];
    unsigned* dst = g_xofs[t][r];
    int n = 0;
#pragma unroll
    for (int w = 0; w < 16; w++) {
        unsigned bits = wp[w];
        while (bits) {
            int b = __ffs(bits) - 1;
            bits &= bits - 1;
            dst[n++] = (unsigned)((w * 32 + b) * 128);
        }
    }
    int np = (n + 7) & ~7;
    while (n < np) dst[n++] = (unsigned)(IN_F * 128);   // dummy -> zero row
    g_xcnt[t][r] = np;
}

// ---------------- global barrier ----------------------------------------------
__device__ __forceinline__ void gbar(int gen, int cta, int tid) {
    __syncthreads();
    if (tid == 0) { __threadfence(); g_arrive[cta] = gen; }
    if (cta == 0 && tid < 32) {
        for (;;) {
            int v0 = g_arrive[tid];
            int v1 = g_arrive[tid + 32];
            int v2 = g_arrive[tid + 64];
            int v3 = g_arrive[tid + 96];
            if (__all_sync(0xFFFFFFFFu,
                           v0 >= gen && v1 >= gen && v2 >= gen && v3 >= gen))
                break;
        }
        if (tid == 0) { __threadfence(); g_release = gen; }
    }
    if (tid == 0) {
        while (g_release < gen) { }
        __threadfence();
    }
    __syncthreads();
}

// ---------------- LIF scalar step ----------------------------------------------
__device__ __forceinline__ unsigned lif1(float& m, float a, float beta) {
    float reset = (m > 1.0f) ? 1.0f : 0.0f;    // spike(m_prev - 1)
    m = beta * m + a - reset;                  // subtract-reset
    return (m > 1.0f) ? 1u : 0u;               // spike(m_new - 1)
}

// ---------------- THE persistent kernel (1024 threads = 32 warps) --------------
__global__ void __launch_bounds__(1024, 1)
snn_phased(const float* __restrict__ W1, const float* __restrict__ b1,
           const float* __restrict__ W2, const float* __restrict__ b2,
           const float* __restrict__ W3, const float* __restrict__ b3)
{
    extern __shared__ float Wsm[];   // phase1: u32 bf16x2 [513][32]; p2/3: [1024][33]
    __shared__ int sr_[3][32];

    const int tid  = threadIdx.x;
    const int cta  = blockIdx.x;
    const int wid  = tid >> 5;
    const int lane = tid & 31;

    const float BETA1 = 0.81873075307798182f;  // exp(-1/5)
    const float BETA2 = 0.90483741803595957f;  // exp(-1/10)
    const float BETA3 = 0.95122942450071402f;  // exp(-1/20)

    int c1 = 0, c2 = 0, c3 = 0;

    // ================= phase 1: layer 1 (64 cols x 32 rows per CTA) ==========
    {
        unsigned* Wb = (unsigned*)Wsm;  // Wb[k*32+l] = bf16x2(W[c0+l][k], W[c0+32+l][k])
        const int cb = cta & 15;        // 16 col-blocks of 64
        const int rg = cta >> 4;        // 8 row-groups of 32
        for (int idx = tid; idx < 32 * IN_F; idx += 1024) {
            int l = idx & 31, k = idx >> 5;
            float v0 = W1[(size_t)(cb * 64 + l) * IN_F + k];
            float v1 = W1[(size_t)(cb * 64 + 32 + l) * IN_F + k];
            unsigned u0 = __float_as_uint(v0);
            u0 = (u0 + 0x7FFFu + ((u0 >> 16) & 1u)) >> 16;
            unsigned u1 = __float_as_uint(v1);
            u1 = ((u1 + 0x7FFFu + ((u1 >> 16) & 1u)) >> 16) << 16;
            Wb[k * 32 + l] = (u0 & 0xFFFFu) | u1;
        }
        if (tid < 32) Wb[IN_F * 32 + tid] = 0u;    // dummy row k = IN_F

        const char* WbL = (const char*)Wb + lane * 4;   // lane base pointer
        const int r0 = rg * 32 + wid;              // warp owns ONE row
        const float bs0 = b1[cb * 64 + lane];
        const float bs1 = b1[cb * 64 + 32 + lane];
        float m0 = 0.f, m1 = 0.f;
        __syncthreads();

        // prefetch t=0 count + first two offset quads (same-address LDG)
        int pn = __ldcg(&g_xcnt[0][r0]);
        uint4 pa = __ldcg((const uint4*)g_xofs[0][r0]);
        uint4 pb = __ldcg((const uint4*)g_xofs[0][r0] + 1);

        for (int t = 0; t < T_STEPS; t++) {
            const int nn = pn;
            uint4 ga = pa, gb = pb;
            if (t + 1 < T_STEPS) {
                pn = __ldcg(&g_xcnt[t + 1][r0]);
                pa = __ldcg((const uint4*)g_xofs[t + 1][r0]);
                pb = __ldcg((const uint4*)g_xofs[t + 1][r0] + 1);
            }
            const uint4* lp = (const uint4*)g_xofs[t][r0];
            // 8 rotating packed bf16x2 accumulators (short chains)
            unsigned ac0 = 0, ac1 = 0, ac2 = 0, ac3 = 0,
                     ac4 = 0, ac5 = 0, ac6 = 0, ac7 = 0;
            const int ng = nn >> 3;            // groups of 8 bits
            for (int j = 0; j < ng; j++) {
                uint4 na = ga, nb = gb;
                if (j + 1 < ng) {
                    na = __ldcg(lp + 2 * j + 2);
                    nb = __ldcg(lp + 2 * j + 3);
                }
#define BADD(A, OFF) { \
                unsigned wv = *(const unsigned*)(WbL + (OFF)); \
                asm("add.rn.bf16x2 %0, %0, %1;" : "+r"(A) : "r"(wv)); }
                BADD(ac0, ga.x)  BADD(ac1, ga.y)
                BADD(ac2, ga.z)  BADD(ac3, ga.w)
                BADD(ac4, gb.x)  BADD(ac5, gb.y)
                BADD(ac6, gb.z)  BADD(ac7, gb.w)
#undef BADD
                ga = na; gb = nb;
            }
            // unpack + fp32 tree sum
            float l01 = __uint_as_float(ac0 << 16) + __uint_as_float(ac1 << 16);
            float l23 = __uint_as_float(ac2 << 16) + __uint_as_float(ac3 << 16);
            float l45 = __uint_as_float(ac4 << 16) + __uint_as_float(ac5 << 16);
            float l67 = __uint_as_float(ac6 << 16) + __uint_as_float(ac7 << 16);
            float h01 = __uint_as_float(ac0 & 0xFFFF0000u) + __uint_as_float(ac1 & 0xFFFF0000u);
            float h23 = __uint_as_float(ac2 & 0xFFFF0000u) + __uint_as_float(ac3 & 0xFFFF0000u);
            float h45 = __uint_as_float(ac4 & 0xFFFF0000u) + __uint_as_float(ac5 & 0xFFFF0000u);
            float h67 = __uint_as_float(ac6 & 0xFFFF0000u) + __uint_as_float(ac7 & 0xFFFF0000u);
            float a0 = bs0 + ((l01 + l23) + (l45 + l67));
            float a1 = bs1 + ((h01 + h23) + (h45 + h67));

            unsigned s0 = lif1(m0, a0, BETA1);
            unsigned s1 = lif1(m1, a1, BETA1);
            unsigned w0 = __ballot_sync(0xFFFFFFFFu, s0);
            unsigned w1 = __ballot_sync(0xFFFFFFFFu, s1);
            if (lane == 0) {
                c1 += __popc(w0) + __popc(w1);
                *(unsigned long long*)&g_b1[t][r0][cb * 2] =
                    ((unsigned long long)w1 << 32) | w0;
            }
        }
    }
    gbar(1, cta, tid);

    // ================= phase 2: layer 2 (32 cols x 64 rows per CTA) ==========
    {
        const int cb = cta & 31;        // 32 col-blocks of 32
        const int rg = cta >> 5;        // 4 row-groups of 64
        for (int idx = tid; idx < 32 * H1; idx += 1024) {
            int n = idx >> 10, k = idx & (H1 - 1);
            Wsm[k * SW2 + n] = W2[(size_t)(cb * 32 + n) * H1 + k];
        }
        const int r0 = rg * 64 + wid * 2;          // warp owns rows r0, r0+1
        const float bsv = b2[cb * 32 + lane];
        float m[2] = {0.f, 0.f};
        __syncthreads();

        unsigned cur[2];
#pragma unroll
        for (int c = 0; c < 2; c++) cur[c] = __ldcg(&g_b1[0][r0 + c][lane]);
        for (int t = 0; t < T_STEPS; t++) {
            unsigned nxt[2] = {0, 0};
            if (t + 1 < T_STEPS) {
#pragma unroll
                for (int c = 0; c < 2; c++)
                    nxt[c] = __ldcg(&g_b1[t + 1][r0 + c][lane]);
            }
#pragma unroll
            for (int i = 0; i < 2; i++) {
                float a = bsv;
                unsigned nz = __ballot_sync(0xFFFFFFFFu, cur[i] != 0u);
                while (nz) {
                    int w = __ffs(nz) - 1;
                    nz &= nz - 1;
                    unsigned bits = __shfl_sync(0xFFFFFFFFu, cur[i], w);
                    while (bits) {
                        int b = __ffs(bits) - 1;
                        bits &= bits - 1;
                        a += Wsm[(w * 32 + b) * SW2 + lane];
                    }
                }
                unsigned s = lif1(m[i], a, BETA2);
                unsigned w0 = __ballot_sync(0xFFFFFFFFu, s);
                if (lane == 0) {
                    c2 += __popc(w0);
                    g_b2[t][r0 + i][cb] = w0;
                }
            }
#pragma unroll
            for (int c = 0; c < 2; c++) cur[c] = nxt[c];
        }
    }
    gbar(2, cta, tid);

    // ================= phase 3: layer 3 (32 cols x 32 rows per CTA) ==========
    {
        const int cb = cta & 15;        // 16 col-blocks of 32
        const int rg = cta >> 4;        // 8 row-groups of 32
        for (int idx = tid; idx < 32 * H2; idx += 1024) {
            int n = idx >> 10, k = idx & (H2 - 1);
            Wsm[k * SW2 + n] = W3[(size_t)(cb * 32 + n) * H2 + k];
        }
        const int r0 = rg * 32 + wid;              // warp owns ONE row
        const float bsv = b3[cb * 32 + lane];
        float m3v = 0.f, msv = 0.f;
        __syncthreads();

        unsigned cur = __ldcg(&g_b2[0][r0][lane]);
        for (int t = 0; t < T_STEPS; t++) {
            unsigned nxt = 0;
            if (t + 1 < T_STEPS) nxt = __ldcg(&g_b2[t + 1][r0][lane]);
            float a = bsv;
            unsigned nz = __ballot_sync(0xFFFFFFFFu, cur != 0u);
            while (nz) {
                int w = __ffs(nz) - 1;
                nz &= nz - 1;
                unsigned bits = __shfl_sync(0xFFFFFFFFu, cur, w);
                while (bits) {
                    int b = __ffs(bits) - 1;
                    bits &= bits - 1;
                    a += Wsm[(w * 32 + b) * SW2 + lane];
                }
            }
            unsigned s = lif1(m3v, a, BETA3);
            msv += m3v;
            unsigned w0 = __ballot_sync(0xFFFFFFFFu, s);
            if (lane == 0) c3 += __popc(w0);
            cur = nxt;
        }
        g_m3sum[(size_t)r0 * H3 + cb * 32 + lane] = msv;
    }

    // ---- exact spike counts ----
    if (lane == 0) { sr_[0][wid] = c1; sr_[1][wid] = c2; sr_[2][wid] = c3; }
    __syncthreads();
    if (tid < 3) {
        int s = 0;
#pragma unroll
        for (int w = 0; w < 32; w++) s += sr_[tid][w];
        atomicAdd(&g_cnt[tid], s);
    }
}

// ---------------- readout -------------------------------------------------------
__global__ void final_kernel(const float* __restrict__ Wr,
                             const float* __restrict__ br,
                             float* __restrict__ out)
{
    const int b = blockIdx.x;
    const int t = threadIdx.x;
    float a0 = 0.f, a1 = 0.f;
    for (int j = t; j < H3; j += 128) {
        float v = g_m3sum[(size_t)b * H3 + j] / (float)T_STEPS;
        a0 = fmaf(v, Wr[j],      a0);
        a1 = fmaf(v, Wr[H3 + j], a1);
    }
    __shared__ float s0[128], s1[128];
    s0[t] = a0; s1[t] = a1;
    __syncthreads();
    for (int o = 64; o > 0; o >>= 1) {
        if (t < o) { s0[t] += s0[t + o]; s1[t] += s1[t + o]; }
        __syncthreads();
    }
    if (t == 0) {
        out[b * 2 + 0] = s0[0] + br[0];
        out[b * 2 + 1] = s1[0] + br[1];
    }
    if (b == 0 && t < 3) {
        float denom = (t == 0) ? (float)((double)T_STEPS * BATCH * H1)
                    : (t == 1) ? (float)((double)T_STEPS * BATCH * H2)
                               : (float)((double)T_STEPS * BATCH * H3);
        out[BATCH * 2 + t] = (float)g_cnt[t] / denom;
    }
}

// ---------------- launch --------------------------------------------------------
extern "C" void kernel_launch(void* const* d_in, const int* in_sizes, int n_in,
                              void* d_out, int out_size)
{
    const float* spikes = (const float*)d_in[0];
    const float* W1 = (const float*)d_in[1];
    const float* b1 = (const float*)d_in[2];
    const float* W2 = (const float*)d_in[3];
    const float* b2 = (const float*)d_in[4];
    const float* W3 = (const float*)d_in[5];
    const float* b3 = (const float*)d_in[6];
    const float* Wr = (const float*)d_in[7];
    const float* br = (const float*)d_in[8];
    float* out = (float*)d_out;

    // phase1 needs (512+1)*32*4 = 65,664 B; phase2/3 need 1024*33*4 = 135,168 B
    const int DSMEM = 1024 * SW2 * 4;
    cudaFuncSetAttribute(snn_phased,
                         cudaFuncAttributeMaxDynamicSharedMemorySize, DSMEM);

    init_kernel<<<1, 256>>>();
    {
        int n = T_STEPS * BATCH * 16;
        build_xbits<<<(n + 255) / 256, 256>>>(spikes);
        build_xidx<<<(T_STEPS * BATCH + 255) / 256, 256>>>();
    }
    snn_phased<<<NCTA, 1024, DSMEM>>>(W1, b1, W2, b2, W3, b3);
    final_kernel<<<BATCH, 128>>>(Wr, br, out);
}